// round 4
// baseline (speedup 1.0000x reference)
#include <cuda_runtime.h>

// MacUnit: out[b, 2*ic+k] = attention[2*ic+k] * f3(data[b, ic])
// f3 = 3 iterations of x += step(x)/3 (tanh-indexed piecewise-linear trig).
//
// R4 strategy: f3 is a FIXED scalar function of one variable for the given
// (angles, velocity, coeff, bias). Kernel 1 tabulates f3 exactly on a 2^20
// grid over [-8, 8] (h = 2^-16, exact in fp32; data is N(0,1) so max|x|~5.7).
// Kernel 2 is then a pure memory-bound gather+lerp+scale map, removing the
// 12x(EX2,RCP,SIN,COS) MUFU wall (85K cyc) from the 16.7M-element hot path.

#define NUM_POINTS 17
#define TAB_LOG2   20
#define TAB_N      (1 << TAB_LOG2)          // 1048576 intervals
#define TAB_SCALE  65536.0f                 // 1/h = 2^16
#define TAB_H      (1.0f / 65536.0f)

__device__ float g_tab[TAB_N + 2];

// ---------------------------------------------------------------------------
// Kernel 1: build table. Exact f3 evaluation (same math as the verified R3
// kernel: register-resident segment table via warp shuffle).
// ---------------------------------------------------------------------------
__global__ __launch_bounds__(256)
void build_table_kernel(const float* __restrict__ angles,
                        const float* __restrict__ velocity,
                        const float* __restrict__ coeff,
                        const float* __restrict__ bias)
{
    const int lane = threadIdx.x & 31;

    float r_vb3 = 0.f, r_dv3 = 0.f, r_ab = 0.f, r_da = 0.f;
    if (lane < 18) {
        int bgn = lane - 8;
        int end = bgn + 1;
        int bw = bgn < 0 ? bgn + NUM_POINTS : bgn;    // torch negative wrap
        int ew = end < 0 ? end + NUM_POINTS : end;
        float vb = __ldg(&velocity[bw]) * (1.0f / 3.0f);
        float ve = __ldg(&velocity[ew]) * (1.0f / 3.0f);
        r_vb3 = vb;
        r_dv3 = ve - vb;
        r_ab  = __ldg(&angles[bw]);
        r_da  = __ldg(&angles[ew]) - r_ab;
    }

    const float c2l = __ldg(coeff) * 2.8853900817779268f;   // 2*log2(e)*c
    const float b2l = __ldg(bias)  * 2.8853900817779268f;   // 2*log2(e)*b

    const int i = blockIdx.x * 256 + threadIdx.x;
    // grid point (exact fp32: -8 + i*2^-16)
    float x = fmaf((float)i, TAB_H, -8.0f);
    bool active = (i <= TAB_N + 1);

    #pragma unroll
    for (int s = 0; s < 3; s++) {
        float e;
        asm("ex2.approx.f32 %0, %1;" : "=f"(e) : "f"(fmaf(x, c2l, b2l)));
        float r;
        asm("rcp.approx.f32 %0, %1;" : "=f"(r) : "f"(e + 1.0f));
        float u = fmaf(r, -17.0f, 17.5f);   // index + 8, in (0.5, 17.5)
        int   si = (int)u;
        float pos = u - (float)si;

        float vb = __shfl_sync(0xffffffffu, r_vb3, si);
        float dv = __shfl_sync(0xffffffffu, r_dv3, si);
        float ab = __shfl_sync(0xffffffffu, r_ab,  si);
        float da = __shfl_sync(0xffffffffu, r_da,  si);
        float velo3 = fmaf(pos, dv, vb);
        float ang   = fmaf(pos, da, ab);
        float sn, cs;
        __sincosf(ang, &sn, &cs);
        x = fmaf(x, fmaf(velo3, sn, 1.0f), velo3 * cs);
    }

    if (active) g_tab[i] = x;
}

// ---------------------------------------------------------------------------
// Kernel 2: memory-bound map. Per float4 of input: 4x (lerp lookup), scale by
// attention, write two float4 of output.
// ---------------------------------------------------------------------------
__global__ __launch_bounds__(256)
void macunit_map_kernel(const float4* __restrict__ data,
                        const float4* __restrict__ att,
                        float4* __restrict__ out)
{
    const int g = blockIdx.x * 256 + threadIdx.x;     // 0 .. B*IN_CH/4 - 1
    const float4 d = data[g];

    float xin[4] = {d.x, d.y, d.z, d.w};
    float y[4];

    #pragma unroll
    for (int j = 0; j < 4; j++) {
        float t = fmaf(xin[j], TAB_SCALE, 8.0f * TAB_SCALE);   // (x+8)/h
        t = fminf(fmaxf(t, 0.0f), (float)TAB_N - 0.001f);
        float fi = floorf(t);
        int   i  = (int)fi;
        float fr = t - fi;
        float v0 = __ldg(&g_tab[i]);
        float v1 = __ldg(&g_tab[i + 1]);
        y[j] = fmaf(fr, v1 - v0, v0);
    }

    const int brow = g >> 7;                          // 128 float4-groups/row
    const int c4   = g & 127;

    const float4 a0 = __ldg(&att[2 * c4]);
    const float4 a1 = __ldg(&att[2 * c4 + 1]);

    float4 o0, o1;
    o0.x = a0.x * y[0];  o0.y = a0.y * y[0];
    o0.z = a0.z * y[1];  o0.w = a0.w * y[1];
    o1.x = a1.x * y[2];  o1.y = a1.y * y[2];
    o1.z = a1.z * y[3];  o1.w = a1.w * y[3];

    const int ob = brow * 256 + 2 * c4;               // 256 float4/output row
    out[ob]     = o0;
    out[ob + 1] = o1;
}

extern "C" void kernel_launch(void* const* d_in, const int* in_sizes, int n_in,
                              void* d_out, int out_size)
{
    const float4* data     = (const float4*)d_in[0];  // [32768, 512] f32
    const float*  angles   = (const float*) d_in[1];  // [17]
    const float*  velocity = (const float*) d_in[2];  // [17]
    const float4* att      = (const float4*)d_in[3];  // [1024] f32
    const float*  coeff    = (const float*) d_in[4];  // [1]
    const float*  bias     = (const float*) d_in[5];  // [1]
    float4* out = (float4*)d_out;

    // Kernel 1: build f3 table (1048578 entries)
    const int build_threads = 256;
    const int build_blocks  = (TAB_N + 2 + build_threads - 1) / build_threads;
    build_table_kernel<<<build_blocks, build_threads>>>(angles, velocity, coeff, bias);

    // Kernel 2: map
    const int total_groups = (32768 * 512) / 4;       // 4,194,304 threads
    const int threads = 256;
    const int blocks = total_groups / threads;        // 16,384
    macunit_map_kernel<<<blocks, threads>>>(data, att, out);
}

// round 5
// speedup vs baseline: 2.2371x; 2.2371x over previous
#include <cuda_runtime.h>

// MacUnit: out[b, 2*ic+k] = attention[2*ic+k] * f3(data[b, ic])
// f3 = 3 iterations of x += step(x)/3 (tanh-indexed piecewise-linear trig).
//
// R5: f3 is a fixed scalar function. Tabulate it on [-4,4] with h=2^-12
// (32769 floats = 128KB) and keep the table in SHARED memory of persistent
// CTAs (R4 showed an L2-resident table costs ~1GB of L2 sector traffic).
// Samples with |x|>=4 (6e-5 of N(0,1)) take an exact MUFU slow path.

#define NUM_POINTS 17
#define TAB_INTERVALS 32768              // 2^15 over [-4,4] => h = 2^-12
#define TAB_ENTRIES   (TAB_INTERVALS + 1)
#define TAB_SCALE     4096.0f            // 1/h
#define TAB_H         (1.0f / 4096.0f)
#define TAB_BYTES     (TAB_ENTRIES * 4)

__device__ float g_tab[TAB_ENTRIES];

// Exact f3 for one value, using gmem tables (rare path + table build).
__device__ __forceinline__ float f3_exact(float x, float c2l, float b2l,
                                          const float* __restrict__ angles,
                                          const float* __restrict__ velocity)
{
    #pragma unroll
    for (int s = 0; s < 3; s++) {
        float e;
        asm("ex2.approx.f32 %0, %1;" : "=f"(e) : "f"(fmaf(x, c2l, b2l)));
        float r;
        asm("rcp.approx.f32 %0, %1;" : "=f"(r) : "f"(e + 1.0f));
        float u = fmaf(r, -17.0f, 17.5f);   // index + 8, in (0.5, 17.5)
        int   si = (int)u;                  // trunc == floor (u > 0)
        float pos = u - (float)si;
        int bgn = si - 8;
        int end = bgn + 1;                  // end < 17 always
        int bw = bgn < 0 ? bgn + NUM_POINTS : bgn;   // torch negative wrap
        int ew = end < 0 ? end + NUM_POINTS : end;
        float vb = __ldg(&velocity[bw]) * (1.0f / 3.0f);
        float ve = __ldg(&velocity[ew]) * (1.0f / 3.0f);
        float ab = __ldg(&angles[bw]);
        float ae = __ldg(&angles[ew]);
        float velo3 = fmaf(pos, ve - vb, vb);
        float ang   = fmaf(pos, ae - ab, ab);
        float sn, cs;
        __sincosf(ang, &sn, &cs);
        x = fmaf(x, fmaf(velo3, sn, 1.0f), velo3 * cs);
    }
    return x;
}

// ---------------------------------------------------------------------------
// Kernel 1: build the [-4,4] table (32769 exact evals — trivial).
// ---------------------------------------------------------------------------
__global__ __launch_bounds__(256)
void build_table_kernel(const float* __restrict__ angles,
                        const float* __restrict__ velocity,
                        const float* __restrict__ coeff,
                        const float* __restrict__ bias)
{
    const float c2l = __ldg(coeff) * 2.8853900817779268f;   // 2*log2(e)*c
    const float b2l = __ldg(bias)  * 2.8853900817779268f;
    const int i = blockIdx.x * 256 + threadIdx.x;
    if (i < TAB_ENTRIES) {
        float x = fmaf((float)i, TAB_H, -4.0f);             // exact in fp32
        g_tab[i] = f3_exact(x, c2l, b2l, angles, velocity);
    }
}

// ---------------------------------------------------------------------------
// Kernel 2: persistent map. Table in shared; double-buffered input loads.
// ---------------------------------------------------------------------------
#define MAP_THREADS 1024
#define MAP_BLOCKS  304                   // ~2 waves on 152 SMs (1 CTA/SM smem)
#define TOTAL_G     ((32768 * 512) / 4)   // 4,194,304 float4 groups

extern __shared__ float s_tab[];

__global__ __launch_bounds__(MAP_THREADS)
void macunit_map_kernel(const float4* __restrict__ data,
                        const float4* __restrict__ att,
                        const float* __restrict__ angles,
                        const float* __restrict__ velocity,
                        const float* __restrict__ coeff,
                        const float* __restrict__ bias,
                        float4* __restrict__ out)
{
    // Stage table into shared memory.
    for (int i = threadIdx.x; i < TAB_ENTRIES; i += MAP_THREADS)
        s_tab[i] = g_tab[i];
    __syncthreads();

    const float c2l = __ldg(coeff) * 2.8853900817779268f;
    const float b2l = __ldg(bias)  * 2.8853900817779268f;

    const int stride = MAP_BLOCKS * MAP_THREADS;
    int g = blockIdx.x * MAP_THREADS + threadIdx.x;

    float4 d = (g < TOTAL_G) ? data[g] : make_float4(0.f, 0.f, 0.f, 0.f);

    while (g < TOTAL_G) {
        // Prefetch next iteration's data (double buffer for MLP).
        const int gn = g + stride;
        float4 dn = (gn < TOTAL_G) ? data[gn] : make_float4(0.f, 0.f, 0.f, 0.f);

        float xin[4] = {d.x, d.y, d.z, d.w};
        float y[4];

        #pragma unroll
        for (int j = 0; j < 4; j++) {
            float x = xin[j];
            if (fabsf(x) < 4.0f) {
                float t = fmaf(x, TAB_SCALE, 4.0f * TAB_SCALE);  // (x+4)/h
                int   i = (int)t;                                 // 0..32767
                float fr = t - (float)i;
                float v0 = s_tab[i];
                float v1 = s_tab[i + 1];
                y[j] = fmaf(fr, v1 - v0, v0);
            } else {
                y[j] = f3_exact(x, c2l, b2l, angles, velocity);   // ~6e-5 of samples
            }
        }

        const int brow = g >> 7;                 // 128 float4-groups/input row
        const int c4   = g & 127;

        const float4 a0 = __ldg(&att[2 * c4]);
        const float4 a1 = __ldg(&att[2 * c4 + 1]);

        float4 o0, o1;
        o0.x = a0.x * y[0];  o0.y = a0.y * y[0];
        o0.z = a0.z * y[1];  o0.w = a0.w * y[1];
        o1.x = a1.x * y[2];  o1.y = a1.y * y[2];
        o1.z = a1.z * y[3];  o1.w = a1.w * y[3];

        const int ob = brow * 256 + 2 * c4;      // 256 float4/output row
        out[ob]     = o0;
        out[ob + 1] = o1;

        g = gn;
        d = dn;
    }
}

extern "C" void kernel_launch(void* const* d_in, const int* in_sizes, int n_in,
                              void* d_out, int out_size)
{
    const float4* data     = (const float4*)d_in[0];  // [32768, 512] f32
    const float*  angles   = (const float*) d_in[1];  // [17]
    const float*  velocity = (const float*) d_in[2];  // [17]
    const float4* att      = (const float4*)d_in[3];  // [1024] f32
    const float*  coeff    = (const float*) d_in[4];  // [1]
    const float*  bias     = (const float*) d_in[5];  // [1]
    float4* out = (float4*)d_out;

    static bool attr_set = false;
    if (!attr_set) {
        cudaFuncSetAttribute(macunit_map_kernel,
                             cudaFuncAttributeMaxDynamicSharedMemorySize,
                             TAB_BYTES);
        attr_set = true;
    }

    build_table_kernel<<<(TAB_ENTRIES + 255) / 256, 256>>>(angles, velocity, coeff, bias);

    macunit_map_kernel<<<MAP_BLOCKS, MAP_THREADS, TAB_BYTES>>>(
        data, att, angles, velocity, coeff, bias, out);
}